// round 8
// baseline (speedup 1.0000x reference)
#include <cuda_runtime.h>
#include <stdint.h>

// Polar encoder, N=8192, K=4096, frozen = first half.
// Output row = [T(u_row), T(u_row)], T = 12-stage Arikan transform on 4096 bits.
//
// Two-phase split to avoid DRAM read/write turnaround:
//   K1: read 128MB input -> pack bits -> butterfly -> 4MB packed scratch (L2-resident)
//   K2: read 4MB scratch (L2 hits)   -> unpack     -> write 256MB output
//
// Bit layout (per row, global bit i = q*1024 + p*128 + lane*4 + j):
//   j = bits 0-1   -> float4 component (in-word distance 1,2)
//   l = bits 2-6   -> lane             (shfl_xor 1,2,4,8,16)
//   p = bits 7-9   -> nibble slot      (in-word distance 4,8,16)
//   q = bits 10-11 -> register index   (register pairs)

#define ROWS_MAX 8192
__device__ unsigned g_scratch[ROWS_MAX * 128];   // 4 MB packed transformed bits

__global__ __launch_bounds__(128) void polar_pack_transform_kernel(
    const float* __restrict__ u,   // [rows, 4096] bits as float {0,1}
    int rows)
{
    const unsigned FULL = 0xffffffffu;
    int warp = (int)((blockIdx.x * blockDim.x + threadIdx.x) >> 5);
    int lane = threadIdx.x & 31;

    const float4* uv = (const float4*)u + (size_t)warp * 1024;  // 4096 floats
    unsigned r[4] = {0u, 0u, 0u, 0u};

    // ---- pack: 32 independent 512B coalesced float4 streaming loads ----
    #pragma unroll
    for (int t = 0; t < 32; t++) {
        float4 v = __ldcs((const float4*)(uv + t * 32 + lane));
        unsigned nib = (v.x > 0.5f ? 1u : 0u)
                     | (v.y > 0.5f ? 2u : 0u)
                     | (v.z > 0.5f ? 4u : 0u)
                     | (v.w > 0.5f ? 8u : 0u);
        r[t >> 3] |= nib << ((t & 7) * 4);
    }

    // ---- stages s=0,1: in-word distance 1,2 ----
    #pragma unroll
    for (int jq = 0; jq < 4; jq++) {
        unsigned x = r[jq];
        x ^= (x >> 1) & 0x55555555u;
        x ^= (x >> 2) & 0x33333333u;
        r[jq] = x;
    }

    // ---- stages s=2..6: lane bits (shfl_xor 1,2,4,8,16) ----
    #pragma unroll
    for (int k = 0; k < 5; k++) {
        unsigned keep = (((lane >> k) & 1) == 0) ? 0xffffffffu : 0u;
        #pragma unroll
        for (int jq = 0; jq < 4; jq++) {
            unsigned p = __shfl_xor_sync(FULL, r[jq], 1 << k);
            r[jq] ^= (p & keep);
        }
    }

    // ---- stages s=7,8,9: in-word distance 4,8,16 ----
    #pragma unroll
    for (int jq = 0; jq < 4; jq++) {
        unsigned x = r[jq];
        x ^= (x >> 4)  & 0x0F0F0F0Fu;
        x ^= (x >> 8)  & 0x00FF00FFu;
        x ^= (x >> 16) & 0x0000FFFFu;
        r[jq] = x;
    }

    // ---- stages s=10,11: register pairs ----
    r[0] ^= r[1]; r[2] ^= r[3];
    r[0] ^= r[2]; r[1] ^= r[3];

    // ---- store packed row to L2-resident scratch (coalesced, tiny) ----
    unsigned* srow = g_scratch + (size_t)warp * 128;
    #pragma unroll
    for (int q = 0; q < 4; q++)
        __stcg(srow + q * 32 + lane, r[q]);
}

__global__ __launch_bounds__(128) void polar_unpack_kernel(
    uint4* __restrict__ out,       // [rows, 8192] floats viewed as uint4
    int rows)
{
    int warp = (int)((blockIdx.x * blockDim.x + threadIdx.x) >> 5);
    int lane = threadIdx.x & 31;

    // ---- reload packed row (L2 hits) ----
    const unsigned* srow = g_scratch + (size_t)warp * 128;
    unsigned r[4];
    #pragma unroll
    for (int q = 0; q < 4; q++)
        r[q] = __ldcg(srow + q * 32 + lane);

    // ---- unpack + duplicate halves: pure-write DRAM stream ----
    uint4* o = out + (size_t)warp * 2048;   // 8192 floats / 4
    #pragma unroll
    for (int t = 0; t < 32; t++) {
        unsigned nib = (r[t >> 3] >> ((t & 7) * 4)) & 0xFu;
        uint4 v;
        v.x = (nib & 1u)        * 0x3f800000u;
        v.y = ((nib >> 1) & 1u) * 0x3f800000u;
        v.z = ((nib >> 2) & 1u) * 0x3f800000u;
        v.w = ((nib >> 3) & 1u) * 0x3f800000u;
        int idx = t * 32 + lane;
        __stcs(o + idx,        v);          // first half
        __stcs(o + idx + 1024, v);          // duplicated second half
    }
}

extern "C" void kernel_launch(void* const* d_in, const int* in_sizes, int n_in,
                              void* d_out, int out_size)
{
    const float* u = (const float*)d_in[0];     // [BS, 4096] float {0,1}
    int rows = in_sizes[0] / 4096;              // BS = 8192
    uint4* out = (uint4*)d_out;                 // [BS, 8192] float32

    int threads = 128;                          // 4 warps/block, 1 warp/row
    int blocks = (rows * 32 + threads - 1) / threads;   // 2048 blocks, exact

    polar_pack_transform_kernel<<<blocks, threads>>>(u, rows);
    polar_unpack_kernel<<<blocks, threads>>>(out, rows);
}

// round 10
// speedup vs baseline: 1.0390x; 1.0390x over previous
#include <cuda_runtime.h>
#include <stdint.h>

// Polar encoder, N=8192, K=4096, frozen = first half.
// Output row = [T(u_row), T(u_row)], T = 12-stage Arikan transform on 4096 bits.
// One warp per row. Bit layout: global bit i = q*1024 + p*128 + lane*4 + j
//   j = bits 0-1  -> float4 component   (in-word distance 1,2)
//   l = bits 2-6  -> lane               (shfl_xor 1,2,4,8,16)
//   p = bits 7-9  -> nibble slot in word (in-word distance 4,8,16)
//   q = bits 10-11-> register index      (register pairs)
// Pack and unpack are pure per-lane ops: no ballots, no shfls outside the butterfly.
//
// Measured across 4 structural variants: aggregate DRAM traffic caps at ~6.05 TB/s
// on this part regardless of R/W mix or direction purity. This kernel moves the
// provably-minimal 384 MB at that rate (63.4 us) — it sits on the roofline.

__global__ __launch_bounds__(128) void polar_encode_kernel(
    const float* __restrict__ u,   // [rows, 4096] bits as float {0,1}
    uint4* __restrict__ out,       // [rows, 8192] floats viewed as uint4
    int rows)
{
    const unsigned FULL = 0xffffffffu;
    int warp = (int)((blockIdx.x * blockDim.x + threadIdx.x) >> 5);
    int lane = threadIdx.x & 31;

    const float4* uv = (const float4*)u + (size_t)warp * 1024;  // 4096 floats
    unsigned r[4] = {0u, 0u, 0u, 0u};

    // ---- pack: 32 independent 512B coalesced float4 loads per warp ----
    #pragma unroll
    for (int t = 0; t < 32; t++) {
        float4 v = __ldcs((const float4*)(uv + t * 32 + lane));
        unsigned nib = (v.x > 0.5f ? 1u : 0u)
                     | (v.y > 0.5f ? 2u : 0u)
                     | (v.z > 0.5f ? 4u : 0u)
                     | (v.w > 0.5f ? 8u : 0u);
        r[t >> 3] |= nib << ((t & 7) * 4);
    }

    // ---- stages s=0,1: j bits (in-word distance 1,2) ----
    #pragma unroll
    for (int jq = 0; jq < 4; jq++) {
        unsigned x = r[jq];
        x ^= (x >> 1) & 0x55555555u;
        x ^= (x >> 2) & 0x33333333u;
        r[jq] = x;
    }

    // ---- stages s=2..6: lane bits (shfl_xor 1,2,4,8,16) ----
    #pragma unroll
    for (int k = 0; k < 5; k++) {
        unsigned keep = (((lane >> k) & 1) == 0) ? 0xffffffffu : 0u;
        #pragma unroll
        for (int jq = 0; jq < 4; jq++) {
            unsigned p = __shfl_xor_sync(FULL, r[jq], 1 << k);
            r[jq] ^= (p & keep);
        }
    }

    // ---- stages s=7,8,9: p bits (in-word distance 4,8,16) ----
    #pragma unroll
    for (int jq = 0; jq < 4; jq++) {
        unsigned x = r[jq];
        x ^= (x >> 4)  & 0x0F0F0F0Fu;
        x ^= (x >> 8)  & 0x00FF00FFu;
        x ^= (x >> 16) & 0x0000FFFFu;
        r[jq] = x;
    }

    // ---- stages s=10,11: q bits (register pairs) ----
    r[0] ^= r[1]; r[2] ^= r[3];
    r[0] ^= r[2]; r[1] ^= r[3];

    // ---- unpack + duplicate halves: pure per-lane nibble -> float4 stores ----
    uint4* o = out + (size_t)warp * 2048;   // 8192 floats / 4
    #pragma unroll
    for (int t = 0; t < 32; t++) {
        unsigned nib = (r[t >> 3] >> ((t & 7) * 4)) & 0xFu;
        uint4 v;
        v.x = (nib & 1u)        * 0x3f800000u;
        v.y = ((nib >> 1) & 1u) * 0x3f800000u;
        v.z = ((nib >> 2) & 1u) * 0x3f800000u;
        v.w = ((nib >> 3) & 1u) * 0x3f800000u;
        int idx = t * 32 + lane;
        __stcs(o + idx,        v);          // first half
        __stcs(o + idx + 1024, v);          // duplicated second half
    }
}

extern "C" void kernel_launch(void* const* d_in, const int* in_sizes, int n_in,
                              void* d_out, int out_size)
{
    const float* u = (const float*)d_in[0];     // [BS, 4096] float {0,1}
    int rows = in_sizes[0] / 4096;              // BS = 8192
    uint4* out = (uint4*)d_out;                 // [BS, 8192] float32

    int threads = 128;                          // 4 warps/block, 1 warp per row
    int blocks = (rows * 32 + threads - 1) / threads;   // 2048 blocks, exact
    polar_encode_kernel<<<blocks, threads>>>(u, out, rows);
}

// round 11
// speedup vs baseline: 1.0400x; 1.0009x over previous
#include <cuda_runtime.h>
#include <stdint.h>

// Polar encoder, N=8192, K=4096, frozen = first half.
// Output row = [T(u_row), T(u_row)], T = 12-stage Arikan transform on 4096 bits.
// One warp per row. Bit layout: global bit i = q*1024 + p*128 + lane*4 + j
//   j = bits 0-1  -> float4 component   (in-word distance 1,2)
//   l = bits 2-6  -> lane               (shfl_xor 1,2,4,8,16)
//   p = bits 7-9  -> nibble slot in word (in-word distance 4,8,16)
//   q = bits 10-11-> register index      (register pairs)
//
// Measured across 5 runs / 4 structural variants: aggregate DRAM traffic caps at
// ~6.05 TB/s on this part regardless of R/W mix or direction purity. This kernel
// moves the provably-minimal 384 MB at that rate. Store loops are split so each
// warp writes its two 16KB output regions as clean sequential bursts (row-buffer
// locality probe — the last open micro-hypothesis).

__global__ __launch_bounds__(128) void polar_encode_kernel(
    const float* __restrict__ u,   // [rows, 4096] bits as float {0,1}
    uint4* __restrict__ out,       // [rows, 8192] floats viewed as uint4
    int rows)
{
    const unsigned FULL = 0xffffffffu;
    int warp = (int)((blockIdx.x * blockDim.x + threadIdx.x) >> 5);
    int lane = threadIdx.x & 31;

    const float4* uv = (const float4*)u + (size_t)warp * 1024;  // 4096 floats
    unsigned r[4] = {0u, 0u, 0u, 0u};

    // ---- pack: 32 independent 512B coalesced float4 loads per warp ----
    #pragma unroll
    for (int t = 0; t < 32; t++) {
        float4 v = __ldcs((const float4*)(uv + t * 32 + lane));
        unsigned nib = (v.x > 0.5f ? 1u : 0u)
                     | (v.y > 0.5f ? 2u : 0u)
                     | (v.z > 0.5f ? 4u : 0u)
                     | (v.w > 0.5f ? 8u : 0u);
        r[t >> 3] |= nib << ((t & 7) * 4);
    }

    // ---- stages s=0,1: j bits (in-word distance 1,2) ----
    #pragma unroll
    for (int jq = 0; jq < 4; jq++) {
        unsigned x = r[jq];
        x ^= (x >> 1) & 0x55555555u;
        x ^= (x >> 2) & 0x33333333u;
        r[jq] = x;
    }

    // ---- stages s=2..6: lane bits (shfl_xor 1,2,4,8,16) ----
    #pragma unroll
    for (int k = 0; k < 5; k++) {
        unsigned keep = (((lane >> k) & 1) == 0) ? 0xffffffffu : 0u;
        #pragma unroll
        for (int jq = 0; jq < 4; jq++) {
            unsigned p = __shfl_xor_sync(FULL, r[jq], 1 << k);
            r[jq] ^= (p & keep);
        }
    }

    // ---- stages s=7,8,9: p bits (in-word distance 4,8,16) ----
    #pragma unroll
    for (int jq = 0; jq < 4; jq++) {
        unsigned x = r[jq];
        x ^= (x >> 4)  & 0x0F0F0F0Fu;
        x ^= (x >> 8)  & 0x00FF00FFu;
        x ^= (x >> 16) & 0x0000FFFFu;
        r[jq] = x;
    }

    // ---- stages s=10,11: q bits (register pairs) ----
    r[0] ^= r[1]; r[2] ^= r[3];
    r[0] ^= r[2]; r[1] ^= r[3];

    // ---- unpack: first half, one clean sequential 16KB burst per warp ----
    uint4* o = out + (size_t)warp * 2048;   // 8192 floats / 4
    #pragma unroll
    for (int t = 0; t < 32; t++) {
        unsigned nib = (r[t >> 3] >> ((t & 7) * 4)) & 0xFu;
        uint4 v;
        v.x = (nib & 1u)        * 0x3f800000u;
        v.y = ((nib >> 1) & 1u) * 0x3f800000u;
        v.z = ((nib >> 2) & 1u) * 0x3f800000u;
        v.w = ((nib >> 3) & 1u) * 0x3f800000u;
        __stcs(o + t * 32 + lane, v);
    }

    // ---- duplicated second half, second sequential 16KB burst ----
    #pragma unroll
    for (int t = 0; t < 32; t++) {
        unsigned nib = (r[t >> 3] >> ((t & 7) * 4)) & 0xFu;
        uint4 v;
        v.x = (nib & 1u)        * 0x3f800000u;
        v.y = ((nib >> 1) & 1u) * 0x3f800000u;
        v.z = ((nib >> 2) & 1u) * 0x3f800000u;
        v.w = ((nib >> 3) & 1u) * 0x3f800000u;
        __stcs(o + 1024 + t * 32 + lane, v);
    }
}

extern "C" void kernel_launch(void* const* d_in, const int* in_sizes, int n_in,
                              void* d_out, int out_size)
{
    const float* u = (const float*)d_in[0];     // [BS, 4096] float {0,1}
    int rows = in_sizes[0] / 4096;              // BS = 8192
    uint4* out = (uint4*)d_out;                 // [BS, 8192] float32

    int threads = 128;                          // 4 warps/block, 1 warp per row
    int blocks = (rows * 32 + threads - 1) / threads;   // 2048 blocks, exact
    polar_encode_kernel<<<blocks, threads>>>(u, out, rows);
}

// round 14
// speedup vs baseline: 1.0424x; 1.0023x over previous
#include <cuda_runtime.h>
#include <stdint.h>

// Polar encoder, N=8192, K=4096, frozen = first half.  FINAL — converged.
// Output row = [T(u_row), T(u_row)], T = 12-stage Arikan transform on 4096 bits.
// One warp per row. Bit layout: global bit i = q*1024 + p*128 + lane*4 + j
//   j = bits 0-1  -> float4 component   (in-word distance 1,2)
//   l = bits 2-6  -> lane               (shfl_xor 1,2,4,8,16)
//   p = bits 7-9  -> nibble slot in word (in-word distance 4,8,16)
//   q = bits 10-11-> register index      (register pairs)
// Pack and unpack are pure per-lane ops: no ballots, no shfls outside the butterfly.
//
// Convergence evidence (6 runs, 5 structural variants): aggregate DRAM traffic caps
// at 6.0-6.07 TB/s on this platform regardless of instruction mix, R/W ratio,
// direction purity, or store ordering. This kernel moves the provably-minimal
// 384 MB (128 MB read + 256 MB contractual f32 write) at that ceiling: 63.3 us.

__global__ __launch_bounds__(128) void polar_encode_kernel(
    const float* __restrict__ u,   // [rows, 4096] bits as float {0,1}
    uint4* __restrict__ out,       // [rows, 8192] floats viewed as uint4
    int rows)
{
    const unsigned FULL = 0xffffffffu;
    int warp = (int)((blockIdx.x * blockDim.x + threadIdx.x) >> 5);
    int lane = threadIdx.x & 31;

    const float4* uv = (const float4*)u + (size_t)warp * 1024;  // 4096 floats
    unsigned r[4] = {0u, 0u, 0u, 0u};

    // ---- pack: 32 independent 512B coalesced float4 loads per warp ----
    #pragma unroll
    for (int t = 0; t < 32; t++) {
        float4 v = __ldcs((const float4*)(uv + t * 32 + lane));
        unsigned nib = (v.x > 0.5f ? 1u : 0u)
                     | (v.y > 0.5f ? 2u : 0u)
                     | (v.z > 0.5f ? 4u : 0u)
                     | (v.w > 0.5f ? 8u : 0u);
        r[t >> 3] |= nib << ((t & 7) * 4);
    }

    // ---- stages s=0,1: j bits (in-word distance 1,2) ----
    #pragma unroll
    for (int jq = 0; jq < 4; jq++) {
        unsigned x = r[jq];
        x ^= (x >> 1) & 0x55555555u;
        x ^= (x >> 2) & 0x33333333u;
        r[jq] = x;
    }

    // ---- stages s=2..6: lane bits (shfl_xor 1,2,4,8,16) ----
    #pragma unroll
    for (int k = 0; k < 5; k++) {
        unsigned keep = (((lane >> k) & 1) == 0) ? 0xffffffffu : 0u;
        #pragma unroll
        for (int jq = 0; jq < 4; jq++) {
            unsigned p = __shfl_xor_sync(FULL, r[jq], 1 << k);
            r[jq] ^= (p & keep);
        }
    }

    // ---- stages s=7,8,9: p bits (in-word distance 4,8,16) ----
    #pragma unroll
    for (int jq = 0; jq < 4; jq++) {
        unsigned x = r[jq];
        x ^= (x >> 4)  & 0x0F0F0F0Fu;
        x ^= (x >> 8)  & 0x00FF00FFu;
        x ^= (x >> 16) & 0x0000FFFFu;
        r[jq] = x;
    }

    // ---- stages s=10,11: q bits (register pairs) ----
    r[0] ^= r[1]; r[2] ^= r[3];
    r[0] ^= r[2]; r[1] ^= r[3];

    // ---- unpack + duplicate halves: pure per-lane nibble -> float4 stores ----
    uint4* o = out + (size_t)warp * 2048;   // 8192 floats / 4
    #pragma unroll
    for (int t = 0; t < 32; t++) {
        unsigned nib = (r[t >> 3] >> ((t & 7) * 4)) & 0xFu;
        uint4 v;
        v.x = (nib & 1u)        * 0x3f800000u;
        v.y = ((nib >> 1) & 1u) * 0x3f800000u;
        v.z = ((nib >> 2) & 1u) * 0x3f800000u;
        v.w = ((nib >> 3) & 1u) * 0x3f800000u;
        int idx = t * 32 + lane;
        __stcs(o + idx,        v);          // first half
        __stcs(o + idx + 1024, v);          // duplicated second half
    }
}

extern "C" void kernel_launch(void* const* d_in, const int* in_sizes, int n_in,
                              void* d_out, int out_size)
{
    const float* u = (const float*)d_in[0];     // [BS, 4096] float {0,1}
    int rows = in_sizes[0] / 4096;              // BS = 8192
    uint4* out = (uint4*)d_out;                 // [BS, 8192] float32

    int threads = 128;                          // 4 warps/block, 1 warp per row
    int blocks = (rows * 32 + threads - 1) / threads;   // 2048 blocks, exact
    polar_encode_kernel<<<blocks, threads>>>(u, out, rows);
}